// round 14
// baseline (speedup 1.0000x reference)
#include <cuda_runtime.h>
#include <math.h>

// maps: [128, 33, 224, 224] fp32  -> d_in[0]
// w1:   [100, 33]            fp32 -> d_in[1]
// w2:   [10, 100]            fp32 -> d_in[2]
// out:  x_sun [128,33] (4224 floats) then x_son stack [9,128,10] (11520 floats)

#define PLANE_ELEMS  (224 * 224)       // 50176
#define PLANE_VEC4   (PLANE_ELEMS / 4) // 12544
#define CHUNKS_PER_PLANE 7
#define CHUNK_VEC4   (PLANE_VEC4 / CHUNKS_PER_PLANE) // 1792, exact
#define POOL_THREADS 256
#define CHUNK_ITERS  (CHUNK_VEC4 / POOL_THREADS)     // 7, exact
#define CHANNELS     33
#define BATCH        128
#define N_PLANES     (BATCH * CHANNELS)              // 4224
#define N_CHUNKS     (N_PLANES * CHUNKS_PER_PLANE)   // 29568
#define X_SUN_ELEMS  (BATCH * CHANNELS)              // 4224
#define PARTIALS_PER_BATCH (CHANNELS * CHUNKS_PER_PLANE) // 231

__device__ float g_partial[N_CHUNKS];   // per-chunk partial sums (deterministic)

// ---------------------------------------------------------------------------
// Kernel 1: partial-sum reduction, one block per 1/7-plane chunk.
// ~25 waves -> wave-quantization waste ~0.1%. Measured ~7.6 TB/s (95% spec).
// ---------------------------------------------------------------------------
__global__ __launch_bounds__(POOL_THREADS, 8)
void pool_kernel(const float4* __restrict__ maps)
{
    const int chunk = blockIdx.x;
    const float4* p = maps + (size_t)chunk * CHUNK_VEC4;
    const int tid = threadIdx.x;

    float s = 0.0f;
#pragma unroll
    for (int i = 0; i < CHUNK_ITERS; i++) {
        float4 v = __ldcs(&p[tid + i * POOL_THREADS]);   // streaming: no reuse
        s += (v.x + v.y) + (v.z + v.w);
    }

#pragma unroll
    for (int off = 16; off > 0; off >>= 1)
        s += __shfl_down_sync(0xFFFFFFFFu, s, off);

    __shared__ float warp_sums[POOL_THREADS / 32];
    const int lane = tid & 31;
    const int wid  = tid >> 5;
    if (lane == 0) warp_sums[wid] = s;
    __syncthreads();

    if (tid == 0) {
        float t = 0.0f;
#pragma unroll
        for (int w = 0; w < POOL_THREADS / 32; w++) t += warp_sums[w];
        g_partial[chunk] = t;
    }
}

// ---------------------------------------------------------------------------
// Kernel 2: MLP head (R12 configuration — best measured: 9.76us).
// One block per batch, 320 threads = 10 warps, one warp per output.
// Phase 0 stages all global data into smem in one parallel load wave.
// ---------------------------------------------------------------------------
__global__ __launch_bounds__(320, 6)
void head_kernel(const float* __restrict__ w1,
                 const float* __restrict__ w2,
                 float* __restrict__ out)
{
#if __CUDA_ARCH__ >= 900
    cudaGridDependencySynchronize();   // PDL: dispatch prefetched vs pool end
#endif
    const int b    = blockIdx.x;
    const int tid  = threadIdx.x;
    const int lane = tid & 31;
    const int wrp  = tid >> 5;      // 0..9 = output index o

    __shared__ float w1s[100 * CHANNELS];   // 3300 floats
    __shared__ float w2s[10 * 100];         // 1000 floats
    __shared__ float ps[PARTIALS_PER_BATCH];// 231 floats
    __shared__ float t33[CHANNELS];
    __shared__ float g[100];
    __shared__ unsigned long long keys[10][104];

    // ---- phase 0: single parallel load wave (maximize MLP) ----
#pragma unroll
    for (int i = tid; i < 100 * CHANNELS; i += 320)
        w1s[i] = w1[i];
#pragma unroll
    for (int i = tid; i < 10 * 100; i += 320)
        w2s[i] = w2[i];
    if (tid < PARTIALS_PER_BATCH)
        ps[tid] = g_partial[b * PARTIALS_PER_BATCH + tid];
    __syncthreads();

    // ---- combine partials -> mean -> x_sun + tanh ----
    if (tid < CHANNELS) {
        float m = 0.0f;
#pragma unroll
        for (int c = 0; c < CHUNKS_PER_PLANE; c++)
            m += ps[tid * CHUNKS_PER_PLANE + c];
        m *= (1.0f / (float)PLANE_ELEMS);
        out[b * CHANNELS + tid] = m;    // x_sun
        t33[tid] = tanhf(m);
    }
    __syncthreads();

    // ---- fc1 + relu (stride-33 smem: conflict-free) ----
    if (tid < 100) {
        float s = 0.0f;
#pragma unroll
        for (int c = 0; c < CHANNELS; c++)
            s = fmaf(t33[c], w1s[tid * CHANNELS + c], s);
        g[tid] = fmaxf(s, 0.0f);
    }
    __syncthreads();

    // ---- per-warp: votes for output o = wrp ----
    const int o = wrp;
    float v0 = g[lane]      * w2s[o * 100 + lane];
    float v1 = g[lane + 32] * w2s[o * 100 + lane + 32];
    float v2 = g[lane + 64] * w2s[o * 100 + lane + 64];
    float v3 = (lane < 4) ? g[lane + 96] * w2s[o * 100 + lane + 96] : 0.0f;

    // monotonic sortable u64 keys (strict total order via index low bits)
    auto mkkey = [](float v, int idx) {
        unsigned int u = __float_as_uint(v);
        u = (u & 0x80000000u) ? ~u : (u | 0x80000000u);
        return ((unsigned long long)u << 32) | (unsigned)idx;
    };
    unsigned long long k0 = mkkey(v0, lane);
    unsigned long long k1 = mkkey(v1, lane + 32);
    unsigned long long k2 = mkkey(v2, lane + 64);
    unsigned long long k3 = mkkey(v3, lane + 96);

    keys[o][lane]      = k0;
    keys[o][lane + 32] = k1;
    keys[o][lane + 64] = k2;
    if (lane < 4) keys[o][lane + 96] = k3;
    __syncwarp();

    // rank = # keys strictly greater (distinct keys -> permutation ranks)
    int r0 = 0, r1 = 0, r2 = 0, r3 = 0;
#pragma unroll 4
    for (int j = 0; j < 100; j++) {
        unsigned long long u = keys[o][j];     // broadcast read
        r0 += (u > k0);
        r1 += (u > k1);
        r2 += (u > k2);
        r3 += (u > k3);
    }
    if (lane >= 4) r3 = 100;                   // non-existent value

    const int KS[8] = {3, 4, 5, 6, 7, 10, 15, 20};
    float sk[9];
#pragma unroll
    for (int k = 0; k < 8; k++) {
        float a = 0.0f;
        if (r0 < KS[k]) a += v0;
        if (r1 < KS[k]) a += v1;
        if (r2 < KS[k]) a += v2;
        if (r3 < KS[k]) a += v3;
        sk[k] = a;
    }
    sk[8] = v0 + v1 + v2 + v3;                 // dense pass

#pragma unroll
    for (int k = 0; k < 9; k++) {
#pragma unroll
        for (int off = 16; off > 0; off >>= 1)
            sk[k] += __shfl_down_sync(0xFFFFFFFFu, sk[k], off);
    }

    if (lane == 0) {
        float* son = out + X_SUN_ELEMS;
#pragma unroll
        for (int k = 0; k < 9; k++)
            son[k * (BATCH * 10) + b * 10 + o] = sk[k];
    }
}

// ---------------------------------------------------------------------------
extern "C" void kernel_launch(void* const* d_in, const int* in_sizes, int n_in,
                              void* d_out, int out_size)
{
    const float4* maps = (const float4*)d_in[0];
    const float*  w1   = (const float*)d_in[1];
    const float*  w2   = (const float*)d_in[2];
    float* out = (float*)d_out;

    pool_kernel<<<N_CHUNKS, POOL_THREADS>>>(maps);

    // head with programmatic dependent launch (hide the launch gap)
    cudaLaunchConfig_t cfg = {};
    cfg.gridDim  = dim3(BATCH, 1, 1);
    cfg.blockDim = dim3(320, 1, 1);
    cfg.dynamicSmemBytes = 0;
    cfg.stream = 0;
    cudaLaunchAttribute attr[1];
    attr[0].id = cudaLaunchAttributeProgrammaticStreamSerialization;
    attr[0].val.programmaticStreamSerializationAllowed = 1;
    cfg.attrs = attr;
    cfg.numAttrs = 1;

    cudaError_t e = cudaLaunchKernelEx(&cfg, head_kernel, w1, w2, out);
    if (e != cudaSuccess) {
        (void)cudaGetLastError();                   // clear, fall back
        head_kernel<<<BATCH, 320>>>(w1, w2, out);
    }
}